// round 16
// baseline (speedup 1.0000x reference)
#include <cuda_runtime.h>
#include <cuda_fp16.h>
#include <math.h>
#include <stdint.h>

#define NTOK 4096
#define DDIM 1024
#define HDIM 4096
#define NEXP 8
#define NGRP 9
#define SHBASE (NEXP * NTOK)
#define XROWS (SHBASE + NTOK)
#define NPERS 304
#define CVT_CTAS 48

// ---------------------------------------------------------------------------
// Device-global scratch
// ---------------------------------------------------------------------------
__device__ __half g_xa  [(size_t)XROWS * DDIM];
__device__ __half g_w1h [(size_t)NEXP * DDIM * HDIM];
__device__ __half g_w2h [(size_t)NEXP * HDIM * DDIM];
__device__ __half g_sw1h[(size_t)DDIM * HDIM];
__device__ __half g_sw2h[(size_t)HDIM * DDIM];
__device__ __half g_h   [(size_t)XROWS * HDIM];
__device__ __half g_y   [(size_t)XROWS * DDIM];
__device__ int    g_cnt [NEXP];
__device__ int    g_te  [2 * NTOK];
__device__ int    g_tp  [2 * NTOK];
__device__ float  g_tw  [2 * NTOK];
__device__ float  g_imp [NEXP];
__device__ int    g_load[NEXP];
__device__ int    g_tkt;
__device__ int    g_rb  [NGRP * 32];   // phase-1 completion per (g, mtile)
__device__ int    g_cvtdone;           // w2/sw2 conversion done counter

// ---------------------------------------------------------------------------
// PTX helpers
// ---------------------------------------------------------------------------
__device__ __forceinline__ void cp_async16(uint32_t s, const void* g) {
    asm volatile("cp.async.cg.shared.global [%0], [%1], 16;\n" :: "r"(s), "l"(g));
}
__device__ __forceinline__ void cp_commit() { asm volatile("cp.async.commit_group;\n"); }
template <int NN> __device__ __forceinline__ void cp_wait() {
    asm volatile("cp.async.wait_group %0;\n" :: "n"(NN));
}
__device__ __forceinline__ void ldsm4(uint32_t* r, uint32_t addr) {
    asm volatile("ldmatrix.sync.aligned.m8n8.x4.shared.b16 {%0,%1,%2,%3}, [%4];\n"
                 : "=r"(r[0]), "=r"(r[1]), "=r"(r[2]), "=r"(r[3]) : "r"(addr));
}
__device__ __forceinline__ void ldsm4t(uint32_t* r, uint32_t addr) {
    asm volatile("ldmatrix.sync.aligned.m8n8.x4.trans.shared.b16 {%0,%1,%2,%3}, [%4];\n"
                 : "=r"(r[0]), "=r"(r[1]), "=r"(r[2]), "=r"(r[3]) : "r"(addr));
}
__device__ __forceinline__ void mma_m16n8k16(float* c, const uint32_t* a, const uint32_t* b) {
    asm volatile(
        "mma.sync.aligned.m16n8k16.row.col.f32.f16.f16.f32 "
        "{%0,%1,%2,%3}, {%4,%5,%6,%7}, {%8,%9}, {%0,%1,%2,%3};\n"
        : "+f"(c[0]), "+f"(c[1]), "+f"(c[2]), "+f"(c[3])
        : "r"(a[0]), "r"(a[1]), "r"(a[2]), "r"(a[3]), "r"(b[0]), "r"(b[1]));
}
__device__ __forceinline__ float gelu_exact(float v) {
    return 0.5f * v * (1.0f + erff(v * 0.70710678118654752440f));
}
__device__ __forceinline__ void cvt_f4(const float* src, __half* dst, size_t off) {
    float4 v = reinterpret_cast<const float4*>(src)[off];
    __half2 h0 = __floats2half2_rn(v.x, v.y);
    __half2 h1 = __floats2half2_rn(v.z, v.w);
    uint2 o;
    o.x = *reinterpret_cast<uint32_t*>(&h0);
    o.y = *reinterpret_cast<uint32_t*>(&h1);
    reinterpret_cast<uint2*>(dst)[off] = o;
}
__device__ __forceinline__ int gld_cg(const int* p) {
    int v;
    asm volatile("ld.global.cg.b32 %0, [%1];" : "=r"(v) : "l"(p));
    return v;
}

// ---------------------------------------------------------------------------
// init
// ---------------------------------------------------------------------------
__global__ void init_kernel() {
    int t = threadIdx.x;   // 640 threads
    if (t < NEXP) { g_cnt[t] = 0; g_imp[t] = 0.f; g_load[t] = 0; }
    if (t == 0) { g_tkt = 0; g_cvtdone = 0; }
    if (t < NGRP * 32) g_rb[t] = 0;
}

// ---------------------------------------------------------------------------
// prep: blocks [0,512) gating; rest convert w1 + sw1
// ---------------------------------------------------------------------------
#define GATE_BLKS 512
#define W1Q ((size_t)NEXP * DDIM * HDIM / 4)
#define S1Q ((size_t)DDIM * HDIM / 4)
#define W2Q ((size_t)NEXP * HDIM * DDIM / 4)
#define S2Q ((size_t)HDIM * DDIM / 4)
#define CVT1_BLKS ((int)((W1Q + S1Q) / 256))
#define PREP_BLKS (GATE_BLKS + CVT1_BLKS)

__global__ void prep_kernel(const float* __restrict__ x,
                            const float* __restrict__ gw,
                            const float* __restrict__ gb,
                            const float* __restrict__ w1,
                            const float* __restrict__ sw1) {
    __shared__ float s_imp[NEXP];
    __shared__ int   s_load[NEXP];

    if (blockIdx.x >= GATE_BLKS) {
        size_t q = (size_t)(blockIdx.x - GATE_BLKS) * 256 + threadIdx.x;
        if (q < W1Q) cvt_f4(w1, g_w1h, q);
        else         cvt_f4(sw1, g_sw1h, q - W1Q);
        return;
    }

    int tid = threadIdx.x;
    if (tid < NEXP) { s_imp[tid] = 0.f; s_load[tid] = 0; }
    __syncthreads();

    int token = blockIdx.x * 8 + (tid >> 5);
    int lane  = tid & 31;

    float acc[NEXP];
#pragma unroll
    for (int e = 0; e < NEXP; e++) acc[e] = 0.f;

    const float* xr = x + (size_t)token * DDIM;
    for (int d = lane; d < DDIM; d += 32) {
        float xv = xr[d];
        const float4* gr = reinterpret_cast<const float4*>(gw + (size_t)d * NEXP);
        float4 g0 = gr[0], g1 = gr[1];
        acc[0] += xv * g0.x; acc[1] += xv * g0.y; acc[2] += xv * g0.z; acc[3] += xv * g0.w;
        acc[4] += xv * g1.x; acc[5] += xv * g1.y; acc[6] += xv * g1.z; acc[7] += xv * g1.w;
    }
#pragma unroll
    for (int e = 0; e < NEXP; e++) {
#pragma unroll
        for (int off = 16; off; off >>= 1)
            acc[e] += __shfl_xor_sync(0xffffffffu, acc[e], off);
    }

    if (lane == 0) {
        float l[NEXP];
        float mx = -1e30f;
#pragma unroll
        for (int e = 0; e < NEXP; e++) { l[e] = acc[e] + gb[e]; mx = fmaxf(mx, l[e]); }
        float p[NEXP], s = 0.f;
#pragma unroll
        for (int e = 0; e < NEXP; e++) { p[e] = expf(l[e] - mx); s += p[e]; }
        float inv = 1.f / s;
#pragma unroll
        for (int e = 0; e < NEXP; e++) atomicAdd(&s_imp[e], p[e] * inv);

        int i0 = 0;
#pragma unroll
        for (int e = 1; e < NEXP; e++) if (l[e] > l[i0]) i0 = e;
        int i1 = (i0 == 0) ? 1 : 0;
#pragma unroll
        for (int e = 0; e < NEXP; e++) if (e != i0 && l[e] > l[i1]) i1 = e;

        float w0 = 1.f / (1.f + expf(l[i1] - l[i0]));
        float w1v = 1.f - w0;

        int p0 = atomicAdd(&g_cnt[i0], 1);
        g_te[2 * token] = i0; g_tp[2 * token] = p0; g_tw[2 * token] = w0;
        int p1 = atomicAdd(&g_cnt[i1], 1);
        g_te[2 * token + 1] = i1; g_tp[2 * token + 1] = p1; g_tw[2 * token + 1] = w1v;
        atomicAdd(&s_load[i0], 1);
        atomicAdd(&s_load[i1], 1);
    }
    __syncthreads();
    if (tid < NEXP) {
        atomicAdd(&g_imp[tid], s_imp[tid]);
        atomicAdd(&g_load[tid], s_load[tid]);
    }
}

// ---------------------------------------------------------------------------
// scatter
// ---------------------------------------------------------------------------
__global__ void scatter_kernel(const float* __restrict__ x) {
    int t = blockIdx.x;
    int tid = threadIdx.x;
    const float4* src = reinterpret_cast<const float4*>(x + (size_t)t * DDIM);
    float4 a = src[2 * tid], b = src[2 * tid + 1];
    __half2 h0 = __floats2half2_rn(a.x, a.y);
    __half2 h1 = __floats2half2_rn(a.z, a.w);
    __half2 h2 = __floats2half2_rn(b.x, b.y);
    __half2 h3 = __floats2half2_rn(b.z, b.w);
    uint4 o;
    o.x = *reinterpret_cast<uint32_t*>(&h0);
    o.y = *reinterpret_cast<uint32_t*>(&h1);
    o.z = *reinterpret_cast<uint32_t*>(&h2);
    o.w = *reinterpret_cast<uint32_t*>(&h3);

    size_t s0 = (size_t)g_te[2 * t] * NTOK + g_tp[2 * t];
    size_t s1 = (size_t)g_te[2 * t + 1] * NTOK + g_tp[2 * t + 1];
    reinterpret_cast<uint4*>(g_xa + s0 * DDIM)[tid] = o;
    reinterpret_cast<uint4*>(g_xa + s1 * DDIM)[tid] = o;
    reinterpret_cast<uint4*>(g_xa + (size_t)(SHBASE + t) * DDIM)[tid] = o;
}

// ---------------------------------------------------------------------------
// GEMM tile body. 256 thr, 8 warps 4x2, K-chunk 64, 3-stage ring.
// PHASE 1: 128x128 tiles (NSHIFT=5). PHASE 2: 128x64 tiles (NSHIFT=4) —
// halved ticket granularity (70us) to shrink the work-stealing tail.
// ---------------------------------------------------------------------------
#define NSTAGE 3
#define A_STG (128 * 72)
#define B_STG (64 * 136)
#define SMEM_GEMM ((NSTAGE * (A_STG + B_STG)) * 2)   // 107520 B

template <int PHASE>
__device__ __forceinline__ void do_tile(
    int g, int rem,
    uint32_t asb, uint32_t bsb,
    const float* __restrict__ bias_e,
    const float* __restrict__ bias_s) {
    constexpr int KDIM   = (PHASE == 1) ? DDIM : HDIM;
    constexpr int LDB    = (PHASE == 1) ? HDIM : DDIM;
    constexpr int CT     = KDIM / 64;
    constexpr int NSHIFT = (PHASE == 1) ? 5 : 4;
    constexpr int NTILES = 1 << NSHIFT;
    constexpr int TILE_N = (PHASE == 1) ? 128 : 64;
    constexpr int BSTR   = (PHASE == 1) ? 136 : 72;   // halfs per B smem row
    constexpr int NTW    = (PHASE == 1) ? 8 : 4;      // n-subtiles per warp
    constexpr int BCH    = TILE_N / 8;                // 16B chunks per B row
    constexpr int BROWS  = 256 / BCH;                 // rows per load pass
    constexpr int BPASS  = 64 / BROWS;

    const int tid  = threadIdx.x;
    const int lane = tid & 31;
    const int warp = tid >> 5;
    const int wm   = warp >> 1;
    const int wn   = warp & 1;

    const int m0   = (rem >> NSHIFT) * 128;
    const int n0   = (rem & (NTILES - 1)) * TILE_N;
    const int cnt  = (g == NEXP) ? NTOK : g_cnt[g];
    const int base = (g == NEXP) ? SHBASE : g * NTOK;

    const __half* __restrict__ Bp =
        (PHASE == 1) ? ((g < NEXP) ? g_w1h + (size_t)g * DDIM * HDIM : g_sw1h)
                     : ((g < NEXP) ? g_w2h + (size_t)g * HDIM * DDIM : g_sw2h);
    const float* __restrict__ bias =
        (g < NEXP) ? bias_e + (size_t)g * LDB : bias_s;
    const __half* __restrict__ Abase =
        ((PHASE == 1) ? g_xa : g_h) + (size_t)base * KDIM;

    const int la_r = tid >> 3;
    const int la_j = tid & 7;
    const int lb_r = tid / BCH;
    const int lb_j = tid % BCH;

    auto load_chunk = [&](int c) {
        const int s = c - (c / NSTAGE) * NSTAGE;
        const int k0 = c * 64;
        uint32_t ab = asb + s * (A_STG * 2);
        uint32_t bb = bsb + s * (B_STG * 2);
#pragma unroll
        for (int jj = 0; jj < 4; jj++) {
            int r = la_r + jj * 32;
            cp_async16(ab + r * 144 + la_j * 16,
                       Abase + (size_t)(m0 + r) * KDIM + k0 + la_j * 8);
        }
#pragma unroll
        for (int jj = 0; jj < BPASS; jj++) {
            int row = lb_r + jj * BROWS;
            cp_async16(bb + row * (BSTR * 2) + lb_j * 16,
                       Bp + (size_t)(k0 + row) * LDB + n0 + lb_j * 8);
        }
        cp_commit();
    };

    load_chunk(0); load_chunk(1);

    float acc[2][NTW][4] = {};

    const int a_rl = lane & 15;
    const int a_cl = (lane >> 4) << 3;
    const int b_rl = lane & 15;
    const int b_cl = wn * (NTW * 8) + ((lane >> 4) << 3);

    for (int c = 0; c < CT; c++) {
        if (c + 1 < CT) cp_wait<1>();
        else            cp_wait<0>();
        __syncthreads();

        if (c + 2 < CT) load_chunk(c + 2);

        const int s = c - (c / NSTAGE) * NSTAGE;
        const uint32_t ab = asb + s * (A_STG * 2);
        const uint32_t bb = bsb + s * (B_STG * 2);

#pragma unroll
        for (int ks = 0; ks < 4; ks++) {
            uint32_t a[2][4], b[NTW / 2][4];
#pragma unroll
            for (int mt = 0; mt < 2; mt++) {
                int r = wm * 32 + mt * 16 + a_rl;
                int col = ks * 16 + a_cl;
                ldsm4(a[mt], ab + r * 144 + col * 2);
            }
#pragma unroll
            for (int np = 0; np < NTW / 2; np++) {
                int row = ks * 16 + b_rl;
                int col = b_cl + np * 16;
                ldsm4t(b[np], bb + row * (BSTR * 2) + col * 2);
            }
#pragma unroll
            for (int mt = 0; mt < 2; mt++)
#pragma unroll
                for (int nt = 0; nt < NTW; nt++)
                    mma_m16n8k16(acc[mt][nt], a[mt], &b[nt >> 1][(nt & 1) * 2]);
        }
    }

    const int lr = lane >> 2;
    const int lc = (lane & 3) * 2;
#pragma unroll
    for (int mt = 0; mt < 2; mt++) {
#pragma unroll
        for (int hh = 0; hh < 2; hh++) {
            int m = m0 + wm * 32 + mt * 16 + lr + hh * 8;
            if (m < cnt) {
                if (PHASE == 1) {
                    __half* hp = g_h + (size_t)(base + m) * HDIM;
#pragma unroll
                    for (int nt = 0; nt < NTW; nt++) {
                        int n = n0 + wn * (NTW * 8) + nt * 8 + lc;
                        float v0 = gelu_exact(acc[mt][nt][hh * 2 + 0] + bias[n]);
                        float v1 = gelu_exact(acc[mt][nt][hh * 2 + 1] + bias[n + 1]);
                        *reinterpret_cast<__half2*>(hp + n) = __floats2half2_rn(v0, v1);
                    }
                } else {
                    __half* yp = g_y + (size_t)(base + m) * DDIM;
#pragma unroll
                    for (int nt = 0; nt < NTW; nt++) {
                        int n = n0 + wn * (NTW * 8) + nt * 8 + lc;
                        float v0 = acc[mt][nt][hh * 2 + 0] + bias[n];
                        float v1 = acc[mt][nt][hh * 2 + 1] + bias[n + 1];
                        *reinterpret_cast<__half2*>(yp + n) = __floats2half2_rn(v0, v1);
                    }
                }
            }
        }
    }

    if (PHASE == 1) {
        __threadfence();
        __syncthreads();
        if (threadIdx.x == 0)
            atomicAdd(&g_rb[g * 32 + (rem >> NSHIFT)], 1);
    }
}

// ---------------------------------------------------------------------------
// Fused persistent GEMM: phase-1 tickets then phase-2 tickets, one kernel.
// First CVT_CTAS blocks convert w2/sw2 before joining the queue.
// ---------------------------------------------------------------------------
__global__ void __launch_bounds__(256, 2) moe_gemm_fused(
    const float* __restrict__ w2f,
    const float* __restrict__ sw2f,
    const float* __restrict__ b1e,
    const float* __restrict__ sb1,
    const float* __restrict__ b2e,
    const float* __restrict__ sb2) {
    const int tid = threadIdx.x;

    if (blockIdx.x < CVT_CTAS) {
        for (size_t q = (size_t)blockIdx.x * 256 + tid; q < W2Q + S2Q;
             q += (size_t)CVT_CTAS * 256) {
            if (q < W2Q) cvt_f4(w2f, g_w2h, q);
            else         cvt_f4(sw2f, g_sw2h, q - W2Q);
        }
        __threadfence();
        __syncthreads();
        if (tid == 0) atomicAdd(&g_cvtdone, 1);
    }

    extern __shared__ __align__(16) __half smem[];
    const uint32_t asb = (uint32_t)__cvta_generic_to_shared(smem);
    const uint32_t bsb = (uint32_t)__cvta_generic_to_shared(smem + NSTAGE * A_STG);
    __shared__ int s_tkt;
    __shared__ int s_cnt[NGRP];

    if (tid < NGRP) s_cnt[tid] = (tid < NEXP) ? g_cnt[tid] : NTOK;
    __syncthreads();

    int mt_g[NGRP], T1 = 0, T2 = 0;
#pragma unroll
    for (int g = 0; g < NGRP; g++) {
        mt_g[g] = (s_cnt[g] + 127) >> 7;
        T1 += mt_g[g] << 5;      // 32 n-tiles of 128
        T2 += mt_g[g] << 4;      // 16 n-tiles of 64
    }
    const int total = T1 + T2;

    for (;;) {
        __syncthreads();
        if (tid == 0) s_tkt = atomicAdd(&g_tkt, 1);
        __syncthreads();
        int t = s_tkt;
        if (t >= total) break;

        if (t < T1) {
            int g = 0, r = t;
#pragma unroll
            for (int q = 0; q < NGRP; q++) {
                int sz = mt_g[q] << 5;
                if (r < sz) { g = q; break; }
                r -= sz;
            }
            do_tile<1>(g, r, asb, bsb, b1e, sb1);
        } else {
            int g = 0, r = t - T1;
#pragma unroll
            for (int q = 0; q < NGRP; q++) {
                int sz = mt_g[q] << 4;
                if (r < sz) { g = q; break; }
                r -= sz;
            }
            if (tid == 0) {
                int ridx = g * 32 + (r >> 4);
                while (gld_cg(&g_cvtdone) < CVT_CTAS ||
                       gld_cg(&g_rb[ridx]) < 32)
                    __nanosleep(128);
            }
            __syncthreads();
            do_tile<2>(g, r, asb, bsb, b2e, sb2);
        }
    }
}

// ---------------------------------------------------------------------------
// Combine + finalize
// ---------------------------------------------------------------------------
__global__ void combine_kernel(float* __restrict__ out) {
    int t = blockIdx.x;
    int i = threadIdx.x;
    float w0 = g_tw[2 * t], w1 = g_tw[2 * t + 1];
    size_t s0 = (size_t)g_te[2 * t] * NTOK + g_tp[2 * t];
    size_t s1 = (size_t)g_te[2 * t + 1] * NTOK + g_tp[2 * t + 1];
    const __half2* y0 = reinterpret_cast<const __half2*>(g_y + s0 * DDIM);
    const __half2* y1 = reinterpret_cast<const __half2*>(g_y + s1 * DDIM);
    const __half2* ys = reinterpret_cast<const __half2*>(g_y + (size_t)(SHBASE + t) * DDIM);
    float2* op = reinterpret_cast<float2*>(out + (size_t)t * DDIM);
#pragma unroll
    for (int j = 0; j < 2; j++) {
        int k = i + j * 256;
        float2 a = __half22float2(y0[k]);
        float2 b = __half22float2(y1[k]);
        float2 c = __half22float2(ys[k]);
        float2 o;
        o.x = w0 * a.x + w1 * b.x + c.x;
        o.y = w0 * a.y + w1 * b.y + c.y;
        op[k] = o;
    }
}

__global__ void finalize_kernel(float* __restrict__ out, int out_size) {
    if (threadIdx.x == 0 && blockIdx.x == 0) {
        float si = 0.f, sl = 0.f, imp[NEXP], ld[NEXP];
#pragma unroll
        for (int e = 0; e < NEXP; e++) {
            imp[e] = g_imp[e]; ld[e] = (float)g_load[e];
            si += imp[e]; sl += ld[e];
        }
        float a = 0.f;
#pragma unroll
        for (int e = 0; e < NEXP; e++) {
            float d = imp[e] / (si + 1e-8f) - ld[e] / (sl + 1e-8f);
            a += d * d;
        }
        out[out_size - 1] = a;
    }
}

// ---------------------------------------------------------------------------
// Launch
// ---------------------------------------------------------------------------
extern "C" void kernel_launch(void* const* d_in, const int* in_sizes, int n_in,
                              void* d_out, int out_size) {
    const float* x      = (const float*)d_in[0];
    const float* gate_w = (const float*)d_in[1];
    const float* gate_b = (const float*)d_in[2];
    const float* w1     = (const float*)d_in[3];
    const float* b1     = (const float*)d_in[4];
    const float* w2     = (const float*)d_in[5];
    const float* b2     = (const float*)d_in[6];
    const float* sw1    = (const float*)d_in[7];
    const float* sb1    = (const float*)d_in[8];
    const float* sw2    = (const float*)d_in[9];
    const float* sb2    = (const float*)d_in[10];
    float* out = (float*)d_out;

    cudaFuncSetAttribute(moe_gemm_fused, cudaFuncAttributeMaxDynamicSharedMemorySize, SMEM_GEMM);

    init_kernel<<<1, 640>>>();
    prep_kernel<<<PREP_BLKS, 256>>>(x, gate_w, gate_b, w1, sw1);
    scatter_kernel<<<NTOK, 128>>>(x);

    moe_gemm_fused<<<NPERS, 256, SMEM_GEMM>>>(w2, sw2, b1, sb1, b2, sb2);

    combine_kernel<<<NTOK, 256>>>(out);
    finalize_kernel<<<1, 32>>>(out, out_size);
}

// round 17
// speedup vs baseline: 1.1027x; 1.1027x over previous
#include <cuda_runtime.h>
#include <cuda_fp16.h>
#include <math.h>
#include <stdint.h>

#define NTOK 4096
#define DDIM 1024
#define HDIM 4096
#define NEXP 8
#define NGRP 9
#define SHBASE (NEXP * NTOK)
#define XROWS (SHBASE + NTOK)
#define NPERS 304
#define CVT_CTAS 48

// ---------------------------------------------------------------------------
// Device-global scratch
// ---------------------------------------------------------------------------
__device__ __half g_xa  [(size_t)XROWS * DDIM];
__device__ __half g_w1h [(size_t)NEXP * DDIM * HDIM];
__device__ __half g_w2h [(size_t)NEXP * HDIM * DDIM];
__device__ __half g_sw1h[(size_t)DDIM * HDIM];
__device__ __half g_sw2h[(size_t)HDIM * DDIM];
__device__ __half g_h   [(size_t)XROWS * HDIM];
__device__ __half g_y   [(size_t)XROWS * DDIM];   // phase-2 K-half 0 (+bias)
__device__ __half g_y2  [(size_t)XROWS * DDIM];   // phase-2 K-half 1
__device__ int    g_cnt [NEXP];
__device__ int    g_te  [2 * NTOK];
__device__ int    g_tp  [2 * NTOK];
__device__ float  g_tw  [2 * NTOK];
__device__ float  g_imp [NEXP];
__device__ int    g_load[NEXP];
__device__ int    g_tkt;
__device__ int    g_rb  [NGRP * 32];   // phase-1 completion per (g, mtile)
__device__ int    g_cvtdone;           // w2/sw2 conversion done counter

// ---------------------------------------------------------------------------
// PTX helpers
// ---------------------------------------------------------------------------
__device__ __forceinline__ void cp_async16(uint32_t s, const void* g) {
    asm volatile("cp.async.cg.shared.global [%0], [%1], 16;\n" :: "r"(s), "l"(g));
}
__device__ __forceinline__ void cp_commit() { asm volatile("cp.async.commit_group;\n"); }
template <int NN> __device__ __forceinline__ void cp_wait() {
    asm volatile("cp.async.wait_group %0;\n" :: "n"(NN));
}
__device__ __forceinline__ void ldsm4(uint32_t* r, uint32_t addr) {
    asm volatile("ldmatrix.sync.aligned.m8n8.x4.shared.b16 {%0,%1,%2,%3}, [%4];\n"
                 : "=r"(r[0]), "=r"(r[1]), "=r"(r[2]), "=r"(r[3]) : "r"(addr));
}
__device__ __forceinline__ void ldsm4t(uint32_t* r, uint32_t addr) {
    asm volatile("ldmatrix.sync.aligned.m8n8.x4.trans.shared.b16 {%0,%1,%2,%3}, [%4];\n"
                 : "=r"(r[0]), "=r"(r[1]), "=r"(r[2]), "=r"(r[3]) : "r"(addr));
}
__device__ __forceinline__ void mma_m16n8k16(float* c, const uint32_t* a, const uint32_t* b) {
    asm volatile(
        "mma.sync.aligned.m16n8k16.row.col.f32.f16.f16.f32 "
        "{%0,%1,%2,%3}, {%4,%5,%6,%7}, {%8,%9}, {%0,%1,%2,%3};\n"
        : "+f"(c[0]), "+f"(c[1]), "+f"(c[2]), "+f"(c[3])
        : "r"(a[0]), "r"(a[1]), "r"(a[2]), "r"(a[3]), "r"(b[0]), "r"(b[1]));
}
__device__ __forceinline__ float gelu_exact(float v) {
    return 0.5f * v * (1.0f + erff(v * 0.70710678118654752440f));
}
__device__ __forceinline__ void cvt_f4(const float* src, __half* dst, size_t off) {
    float4 v = reinterpret_cast<const float4*>(src)[off];
    __half2 h0 = __floats2half2_rn(v.x, v.y);
    __half2 h1 = __floats2half2_rn(v.z, v.w);
    uint2 o;
    o.x = *reinterpret_cast<uint32_t*>(&h0);
    o.y = *reinterpret_cast<uint32_t*>(&h1);
    reinterpret_cast<uint2*>(dst)[off] = o;
}
__device__ __forceinline__ int gld_cg(const int* p) {
    int v;
    asm volatile("ld.global.cg.b32 %0, [%1];" : "=r"(v) : "l"(p));
    return v;
}

// ---------------------------------------------------------------------------
// init
// ---------------------------------------------------------------------------
__global__ void init_kernel() {
    int t = threadIdx.x;   // 640 threads
    if (t < NEXP) { g_cnt[t] = 0; g_imp[t] = 0.f; g_load[t] = 0; }
    if (t == 0) { g_tkt = 0; g_cvtdone = 0; }
    if (t < NGRP * 32) g_rb[t] = 0;
}

// ---------------------------------------------------------------------------
// prep: blocks [0,512) gating+scatter (8 tokens/block, 1 warp/token);
//       rest convert w1 + sw1
// ---------------------------------------------------------------------------
#define GATE_BLKS 512
#define W1Q ((size_t)NEXP * DDIM * HDIM / 4)
#define S1Q ((size_t)DDIM * HDIM / 4)
#define W2Q ((size_t)NEXP * HDIM * DDIM / 4)
#define S2Q ((size_t)HDIM * DDIM / 4)
#define CVT1_BLKS ((int)((W1Q + S1Q) / 256))
#define PREP_BLKS (GATE_BLKS + CVT1_BLKS)

__global__ void prep_kernel(const float* __restrict__ x,
                            const float* __restrict__ gw,
                            const float* __restrict__ gb,
                            const float* __restrict__ w1,
                            const float* __restrict__ sw1) {
    __shared__ float s_imp[NEXP];
    __shared__ int   s_load[NEXP];

    if (blockIdx.x >= GATE_BLKS) {
        size_t q = (size_t)(blockIdx.x - GATE_BLKS) * 256 + threadIdx.x;
        if (q < W1Q) cvt_f4(w1, g_w1h, q);
        else         cvt_f4(sw1, g_sw1h, q - W1Q);
        return;
    }

    int tid = threadIdx.x;
    if (tid < NEXP) { s_imp[tid] = 0.f; s_load[tid] = 0; }
    __syncthreads();

    int token = blockIdx.x * 8 + (tid >> 5);
    int lane  = tid & 31;

    float acc[NEXP];
#pragma unroll
    for (int e = 0; e < NEXP; e++) acc[e] = 0.f;

    const float* xr = x + (size_t)token * DDIM;
    for (int d = lane; d < DDIM; d += 32) {
        float xv = xr[d];
        const float4* gr = reinterpret_cast<const float4*>(gw + (size_t)d * NEXP);
        float4 g0 = gr[0], g1 = gr[1];
        acc[0] += xv * g0.x; acc[1] += xv * g0.y; acc[2] += xv * g0.z; acc[3] += xv * g0.w;
        acc[4] += xv * g1.x; acc[5] += xv * g1.y; acc[6] += xv * g1.z; acc[7] += xv * g1.w;
    }
#pragma unroll
    for (int e = 0; e < NEXP; e++) {
#pragma unroll
        for (int off = 16; off; off >>= 1)
            acc[e] += __shfl_xor_sync(0xffffffffu, acc[e], off);
    }

    int s0i = 0, s1i = 0;
    if (lane == 0) {
        float l[NEXP];
        float mx = -1e30f;
#pragma unroll
        for (int e = 0; e < NEXP; e++) { l[e] = acc[e] + gb[e]; mx = fmaxf(mx, l[e]); }
        float p[NEXP], s = 0.f;
#pragma unroll
        for (int e = 0; e < NEXP; e++) { p[e] = expf(l[e] - mx); s += p[e]; }
        float inv = 1.f / s;
#pragma unroll
        for (int e = 0; e < NEXP; e++) atomicAdd(&s_imp[e], p[e] * inv);

        int i0 = 0;
#pragma unroll
        for (int e = 1; e < NEXP; e++) if (l[e] > l[i0]) i0 = e;
        int i1 = (i0 == 0) ? 1 : 0;
#pragma unroll
        for (int e = 0; e < NEXP; e++) if (e != i0 && l[e] > l[i1]) i1 = e;

        float w0 = 1.f / (1.f + expf(l[i1] - l[i0]));
        float w1v = 1.f - w0;

        int p0 = atomicAdd(&g_cnt[i0], 1);
        g_te[2 * token] = i0; g_tp[2 * token] = p0; g_tw[2 * token] = w0;
        int p1 = atomicAdd(&g_cnt[i1], 1);
        g_te[2 * token + 1] = i1; g_tp[2 * token + 1] = p1; g_tw[2 * token + 1] = w1v;
        atomicAdd(&s_load[i0], 1);
        atomicAdd(&s_load[i1], 1);

        s0i = i0 * NTOK + p0;
        s1i = i1 * NTOK + p1;
    }
    // scatter this token's row (warp-wide) to 2 expert slots + shared slot
    s0i = __shfl_sync(0xffffffffu, s0i, 0);
    s1i = __shfl_sync(0xffffffffu, s1i, 0);
    {
        const float4* src = reinterpret_cast<const float4*>(xr);
        uint4* d0 = reinterpret_cast<uint4*>(g_xa + (size_t)s0i * DDIM);
        uint4* d1 = reinterpret_cast<uint4*>(g_xa + (size_t)s1i * DDIM);
        uint4* ds = reinterpret_cast<uint4*>(g_xa + (size_t)(SHBASE + token) * DDIM);
#pragma unroll
        for (int p = 0; p < 4; p++) {
            int i = p * 32 + lane;                // 128 uint4 chunks per row
            float4 a = src[2 * i], b = src[2 * i + 1];
            __half2 h0 = __floats2half2_rn(a.x, a.y);
            __half2 h1 = __floats2half2_rn(a.z, a.w);
            __half2 h2 = __floats2half2_rn(b.x, b.y);
            __half2 h3 = __floats2half2_rn(b.z, b.w);
            uint4 o;
            o.x = *reinterpret_cast<uint32_t*>(&h0);
            o.y = *reinterpret_cast<uint32_t*>(&h1);
            o.z = *reinterpret_cast<uint32_t*>(&h2);
            o.w = *reinterpret_cast<uint32_t*>(&h3);
            d0[i] = o; d1[i] = o; ds[i] = o;
        }
    }
    __syncthreads();
    if (tid < NEXP) {
        atomicAdd(&g_imp[tid], s_imp[tid]);
        atomicAdd(&g_load[tid], s_load[tid]);
    }
}

// ---------------------------------------------------------------------------
// GEMM tile body (r13 shape: 256 thr, 8 warps 4x2, 128x128 tile, K-chunk 64,
// 3-stage ring). PHASE 2 runs as split-K halves: kbase selects the K range,
// khalf selects output buffer (g_y with bias / g_y2 without).
// ---------------------------------------------------------------------------
#define NSTAGE 3
#define A_STG (128 * 72)
#define B_STG (64 * 136)
#define SMEM_GEMM ((NSTAGE * (A_STG + B_STG)) * 2)   // 107520 B

template <int PHASE>
__device__ __forceinline__ void do_tile(
    int g, int mtile, int ntile, int khalf,
    uint32_t asb, uint32_t bsb,
    const float* __restrict__ bias_e,
    const float* __restrict__ bias_s) {
    constexpr int KDIM = (PHASE == 1) ? DDIM : HDIM;
    constexpr int LDB  = (PHASE == 1) ? HDIM : DDIM;
    constexpr int CT   = (PHASE == 1) ? 16 : 32;      // chunks in this tile

    const int tid  = threadIdx.x;
    const int lane = tid & 31;
    const int warp = tid >> 5;
    const int wm   = warp >> 1;
    const int wn   = warp & 1;

    const int kbase = (PHASE == 1) ? 0 : khalf * 32;  // chunk offset
    const int m0    = mtile * 128;
    const int n0    = ntile * 128;
    const int cnt   = (g == NEXP) ? NTOK : g_cnt[g];
    const int base  = (g == NEXP) ? SHBASE : g * NTOK;

    const __half* __restrict__ Bp =
        (PHASE == 1) ? ((g < NEXP) ? g_w1h + (size_t)g * DDIM * HDIM : g_sw1h)
                     : ((g < NEXP) ? g_w2h + (size_t)g * HDIM * DDIM : g_sw2h);
    const float* __restrict__ bias =
        (g < NEXP) ? bias_e + (size_t)g * LDB : bias_s;
    const __half* __restrict__ Abase =
        ((PHASE == 1) ? g_xa : g_h) + (size_t)base * KDIM;

    const int la_r = tid >> 3;
    const int la_j = tid & 7;
    const int lb_r = tid >> 4;
    const int lb_j = tid & 15;

    auto load_chunk = [&](int c) {
        const int s = c - (c / NSTAGE) * NSTAGE;
        const int k0 = (kbase + c) * 64;
        uint32_t ab = asb + s * (A_STG * 2);
        uint32_t bb = bsb + s * (B_STG * 2);
#pragma unroll
        for (int jj = 0; jj < 4; jj++) {
            int r = la_r + jj * 32;
            cp_async16(ab + r * 144 + la_j * 16,
                       Abase + (size_t)(m0 + r) * KDIM + k0 + la_j * 8);
        }
#pragma unroll
        for (int jj = 0; jj < 4; jj++) {
            int row = lb_r + jj * 16;
            cp_async16(bb + row * 272 + lb_j * 16,
                       Bp + (size_t)(k0 + row) * LDB + n0 + lb_j * 8);
        }
        cp_commit();
    };

    load_chunk(0); load_chunk(1);

    float acc[2][8][4] = {};

    const int a_rl = lane & 15;
    const int a_cl = (lane >> 4) << 3;
    const int b_rl = lane & 15;
    const int b_cl = wn * 64 + ((lane >> 4) << 3);

    for (int c = 0; c < CT; c++) {
        if (c + 1 < CT) cp_wait<1>();
        else            cp_wait<0>();
        __syncthreads();

        if (c + 2 < CT) load_chunk(c + 2);

        const int s = c - (c / NSTAGE) * NSTAGE;
        const uint32_t ab = asb + s * (A_STG * 2);
        const uint32_t bb = bsb + s * (B_STG * 2);

#pragma unroll
        for (int ks = 0; ks < 4; ks++) {
            uint32_t a[2][4], b[4][4];
#pragma unroll
            for (int mt = 0; mt < 2; mt++) {
                int r = wm * 32 + mt * 16 + a_rl;
                int col = ks * 16 + a_cl;
                ldsm4(a[mt], ab + r * 144 + col * 2);
            }
#pragma unroll
            for (int np = 0; np < 4; np++) {
                int row = ks * 16 + b_rl;
                int col = b_cl + np * 16;
                ldsm4t(b[np], bb + row * 272 + col * 2);
            }
#pragma unroll
            for (int mt = 0; mt < 2; mt++)
#pragma unroll
                for (int nt = 0; nt < 8; nt++)
                    mma_m16n8k16(acc[mt][nt], a[mt], &b[nt >> 1][(nt & 1) * 2]);
        }
    }

    const int lr = lane >> 2;
    const int lc = (lane & 3) * 2;
#pragma unroll
    for (int mt = 0; mt < 2; mt++) {
#pragma unroll
        for (int hh = 0; hh < 2; hh++) {
            int m = m0 + wm * 32 + mt * 16 + lr + hh * 8;
            if (m < cnt) {
                if (PHASE == 1) {
                    __half* hp = g_h + (size_t)(base + m) * HDIM;
#pragma unroll
                    for (int nt = 0; nt < 8; nt++) {
                        int n = n0 + wn * 64 + nt * 8 + lc;
                        float v0 = gelu_exact(acc[mt][nt][hh * 2 + 0] + bias[n]);
                        float v1 = gelu_exact(acc[mt][nt][hh * 2 + 1] + bias[n + 1]);
                        *reinterpret_cast<__half2*>(hp + n) = __floats2half2_rn(v0, v1);
                    }
                } else {
                    __half* yp = (khalf ? g_y2 : g_y) + (size_t)(base + m) * DDIM;
#pragma unroll
                    for (int nt = 0; nt < 8; nt++) {
                        int n = n0 + wn * 64 + nt * 8 + lc;
                        float b0 = khalf ? 0.f : bias[n];
                        float b1 = khalf ? 0.f : bias[n + 1];
                        float v0 = acc[mt][nt][hh * 2 + 0] + b0;
                        float v1 = acc[mt][nt][hh * 2 + 1] + b1;
                        *reinterpret_cast<__half2*>(yp + n) = __floats2half2_rn(v0, v1);
                    }
                }
            }
        }
    }

    if (PHASE == 1) {
        __threadfence();
        __syncthreads();
        if (threadIdx.x == 0)
            atomicAdd(&g_rb[g * 32 + mtile], 1);
    }
}

// ---------------------------------------------------------------------------
// Fused persistent GEMM: phase-1 tickets then phase-2 split-K tickets.
// First CVT_CTAS blocks convert w2/sw2 before joining the queue.
// ---------------------------------------------------------------------------
__global__ void __launch_bounds__(256, 2) moe_gemm_fused(
    const float* __restrict__ w2f,
    const float* __restrict__ sw2f,
    const float* __restrict__ b1e,
    const float* __restrict__ sb1,
    const float* __restrict__ b2e,
    const float* __restrict__ sb2) {
    const int tid = threadIdx.x;

    if (blockIdx.x < CVT_CTAS) {
        for (size_t q = (size_t)blockIdx.x * 256 + tid; q < W2Q + S2Q;
             q += (size_t)CVT_CTAS * 256) {
            if (q < W2Q) cvt_f4(w2f, g_w2h, q);
            else         cvt_f4(sw2f, g_sw2h, q - W2Q);
        }
        __threadfence();
        __syncthreads();
        if (tid == 0) atomicAdd(&g_cvtdone, 1);
    }

    extern __shared__ __align__(16) __half smem[];
    const uint32_t asb = (uint32_t)__cvta_generic_to_shared(smem);
    const uint32_t bsb = (uint32_t)__cvta_generic_to_shared(smem + NSTAGE * A_STG);
    __shared__ int s_tkt;
    __shared__ int s_cnt[NGRP];

    if (tid < NGRP) s_cnt[tid] = (tid < NEXP) ? g_cnt[tid] : NTOK;
    __syncthreads();

    int mt_g[NGRP], T1 = 0, T2 = 0;
#pragma unroll
    for (int g = 0; g < NGRP; g++) {
        mt_g[g] = (s_cnt[g] + 127) >> 7;
        T1 += mt_g[g] << 5;      // 32 n-tiles of 128
        T2 += mt_g[g] << 4;      // 8 n-tiles x 2 K-halves
    }
    const int total = T1 + T2;

    for (;;) {
        __syncthreads();
        if (tid == 0) s_tkt = atomicAdd(&g_tkt, 1);
        __syncthreads();
        int t = s_tkt;
        if (t >= total) break;

        if (t < T1) {
            int g = 0, r = t;
#pragma unroll
            for (int q = 0; q < NGRP; q++) {
                int sz = mt_g[q] << 5;
                if (r < sz) { g = q; break; }
                r -= sz;
            }
            do_tile<1>(g, r >> 5, r & 31, 0, asb, bsb, b1e, sb1);
        } else {
            int g = 0, r = t - T1;
#pragma unroll
            for (int q = 0; q < NGRP; q++) {
                int sz = mt_g[q] << 4;
                if (r < sz) { g = q; break; }
                r -= sz;
            }
            const int mtile = r >> 4;
            const int ntile = r & 7;
            const int khalf = (r >> 3) & 1;
            if (tid == 0) {
                int ridx = g * 32 + mtile;
                while (gld_cg(&g_cvtdone) < CVT_CTAS ||
                       gld_cg(&g_rb[ridx]) < 32)
                    __nanosleep(128);
            }
            __syncthreads();
            do_tile<2>(g, mtile, ntile, khalf, asb, bsb, b2e, sb2);
        }
    }
}

// ---------------------------------------------------------------------------
// Combine (sums split-K halves) + finalize
// ---------------------------------------------------------------------------
__global__ void combine_kernel(float* __restrict__ out) {
    int t = blockIdx.x;
    int i = threadIdx.x;
    float w0 = g_tw[2 * t], w1 = g_tw[2 * t + 1];
    size_t s0 = (size_t)g_te[2 * t] * NTOK + g_tp[2 * t];
    size_t s1 = (size_t)g_te[2 * t + 1] * NTOK + g_tp[2 * t + 1];
    size_t ss = (size_t)(SHBASE + t);
    const __half2* ya0 = reinterpret_cast<const __half2*>(g_y  + s0 * DDIM);
    const __half2* yb0 = reinterpret_cast<const __half2*>(g_y2 + s0 * DDIM);
    const __half2* ya1 = reinterpret_cast<const __half2*>(g_y  + s1 * DDIM);
    const __half2* yb1 = reinterpret_cast<const __half2*>(g_y2 + s1 * DDIM);
    const __half2* yas = reinterpret_cast<const __half2*>(g_y  + ss * DDIM);
    const __half2* ybs = reinterpret_cast<const __half2*>(g_y2 + ss * DDIM);
    float2* op = reinterpret_cast<float2*>(out + (size_t)t * DDIM);
#pragma unroll
    for (int j = 0; j < 2; j++) {
        int k = i + j * 256;
        float2 a0 = __half22float2(ya0[k]), b0 = __half22float2(yb0[k]);
        float2 a1 = __half22float2(ya1[k]), b1 = __half22float2(yb1[k]);
        float2 as = __half22float2(yas[k]), bs = __half22float2(ybs[k]);
        float2 o;
        o.x = w0 * (a0.x + b0.x) + w1 * (a1.x + b1.x) + (as.x + bs.x);
        o.y = w0 * (a0.y + b0.y) + w1 * (a1.y + b1.y) + (as.y + bs.y);
        op[k] = o;
    }
}

__global__ void finalize_kernel(float* __restrict__ out, int out_size) {
    if (threadIdx.x == 0 && blockIdx.x == 0) {
        float si = 0.f, sl = 0.f, imp[NEXP], ld[NEXP];
#pragma unroll
        for (int e = 0; e < NEXP; e++) {
            imp[e] = g_imp[e]; ld[e] = (float)g_load[e];
            si += imp[e]; sl += ld[e];
        }
        float a = 0.f;
#pragma unroll
        for (int e = 0; e < NEXP; e++) {
            float d = imp[e] / (si + 1e-8f) - ld[e] / (sl + 1e-8f);
            a += d * d;
        }
        out[out_size - 1] = a;
    }
}

// ---------------------------------------------------------------------------
// Launch: init(1) prep+scatter(2) fused-gemm(3) combine(4) finalize(5)
// ---------------------------------------------------------------------------
extern "C" void kernel_launch(void* const* d_in, const int* in_sizes, int n_in,
                              void* d_out, int out_size) {
    const float* x      = (const float*)d_in[0];
    const float* gate_w = (const float*)d_in[1];
    const float* gate_b = (const float*)d_in[2];
    const float* w1     = (const float*)d_in[3];
    const float* b1     = (const float*)d_in[4];
    const float* w2     = (const float*)d_in[5];
    const float* b2     = (const float*)d_in[6];
    const float* sw1    = (const float*)d_in[7];
    const float* sb1    = (const float*)d_in[8];
    const float* sw2    = (const float*)d_in[9];
    const float* sb2    = (const float*)d_in[10];
    float* out = (float*)d_out;

    cudaFuncSetAttribute(moe_gemm_fused, cudaFuncAttributeMaxDynamicSharedMemorySize, SMEM_GEMM);

    init_kernel<<<1, 640>>>();
    prep_kernel<<<PREP_BLKS, 256>>>(x, gate_w, gate_b, w1, sw1);

    moe_gemm_fused<<<NPERS, 256, SMEM_GEMM>>>(w2, sw2, b1, sb1, b2, sb2);

    combine_kernel<<<NTOK, 256>>>(out);
    finalize_kernel<<<1, 32>>>(out, out_size);
}